// round 2
// baseline (speedup 1.0000x reference)
#include <cuda_runtime.h>
#include <math.h>

#define FEAT 1040
#define NHEADS 8
#define DHEAD 130
#define NNODES 30000
#define MAXEDGES 240000
#define NE2MAX (MAXEDGES + NNODES)
#define NGRAPHS 64
#define NEG_SLOPE 0.2f
#define BN_EPS 1e-5f

// ---------------- scratch (device globals; no allocation allowed) ----------------
__device__ float g_xh[NNODES * FEAT];
__device__ float g_att[NNODES * FEAT];
__device__ float g_h0[NNODES * FEAT];
__device__ float g_h1[NNODES * FEAT];
__device__ float g_as[NNODES * NHEADS];
__device__ float g_ad[NNODES * NHEADS];
__device__ unsigned int g_emax[NNODES * NHEADS];
__device__ float g_denom[NNODES * NHEADS];
__device__ float g_ex[NE2MAX * NHEADS];
__device__ float g_pooled[NGRAPHS * FEAT];
__device__ float g_counts[NGRAPHS];

// ---------------- helpers ----------------
__device__ __forceinline__ unsigned int f2key(float v) {
    unsigned int u = __float_as_uint(v);
    return (u & 0x80000000u) ? ~u : (u | 0x80000000u);
}
__device__ __forceinline__ float key2f(unsigned int k) {
    return (k & 0x80000000u) ? __uint_as_float(k ^ 0x80000000u) : __uint_as_float(~k);
}

__device__ __forceinline__ unsigned long long pack2(float lo, float hi) {
    unsigned long long r;
    asm("mov.b64 %0, {%1, %2};" : "=l"(r) : "f"(lo), "f"(hi));
    return r;
}
__device__ __forceinline__ unsigned long long ffma2(unsigned long long a,
                                                    unsigned long long b,
                                                    unsigned long long c) {
    unsigned long long d;
    asm("fma.rn.f32x2 %0, %1, %2, %3;" : "=l"(d) : "l"(a), "l"(b), "l"(c));
    return d;
}
__device__ __forceinline__ float2 unpack2(unsigned long long v) {
    float2 f;
    asm("mov.b64 {%0, %1}, %2;" : "=f"(f.x), "=f"(f.y) : "l"(v));
    return f;
}

__global__ void zero_f32(float* p, int n) {
    int i = blockIdx.x * blockDim.x + threadIdx.x;
    if (i < n) p[i] = 0.0f;
}
__global__ void zero_u32(unsigned int* p, int n) {
    int i = blockIdx.x * blockDim.x + threadIdx.x;
    if (i < n) p[i] = 0u;
}

// ---------------- GEMM: C[M,N] = A[M,K] @ B[K,N], fp32 via f32x2 packed FMA ----------
// 128x128 tile, BK=16, 256 threads, 8x8 per-thread register tile.
#define BM 128
#define BN 128
#define BK 16
__global__ __launch_bounds__(256) void sgemm_f32x2_kernel(
    const float* __restrict__ A, const float* __restrict__ B, float* __restrict__ C,
    int M, int N, int K)
{
    __shared__ float As[BK][BM];   // transposed A slab
    __shared__ float Bs[BK][BN];

    int tid = threadIdx.x;
    int tx = tid & 15;            // 0..15 -> 8 cols each
    int ty = tid >> 4;            // 0..15 -> 8 rows each
    int row0 = blockIdx.y * BM;
    int col0 = blockIdx.x * BN;

    // A-load mapping: 512 float4 per slab, 2 per thread
    int a_lin0 = tid;             // + it*256
    // B-load mapping: 512 float4 per slab, 2 per thread
    // lin: br = lin>>5 (0..15), bc = (lin&31)*4

    unsigned long long acc[8][4];
#pragma unroll
    for (int i = 0; i < 8; i++)
#pragma unroll
        for (int j = 0; j < 4; j++) acc[i][j] = 0ull;

    float4 pa[2], pb[2];
    // prefetch slab 0
    {
#pragma unroll
        for (int it = 0; it < 2; it++) {
            int lin = a_lin0 + it * 256;
            int ar = lin >> 2, ac = (lin & 3) * 4;
            int gr = row0 + ar;
            pa[it] = make_float4(0.f, 0.f, 0.f, 0.f);
            if (gr < M) pa[it] = *(const float4*)&A[(size_t)gr * K + ac];
#pragma unroll
        }
#pragma unroll
        for (int it = 0; it < 2; it++) {
            int lin = tid + it * 256;
            int br = lin >> 5, bc = (lin & 31) * 4;
            int gc = col0 + bc;
            pb[it] = make_float4(0.f, 0.f, 0.f, 0.f);
            if (gc < N) pb[it] = *(const float4*)&B[(size_t)br * N + gc];
        }
    }

    int nk0 = K / BK;   // K=1040 divisible by 16
    for (int s = 0; s < nk0; s++) {
        // store prefetched slab to smem
#pragma unroll
        for (int it = 0; it < 2; it++) {
            int lin = a_lin0 + it * 256;
            int ar = lin >> 2, ac = (lin & 3) * 4;
            As[ac + 0][ar] = pa[it].x;
            As[ac + 1][ar] = pa[it].y;
            As[ac + 2][ar] = pa[it].z;
            As[ac + 3][ar] = pa[it].w;
        }
#pragma unroll
        for (int it = 0; it < 2; it++) {
            int lin = tid + it * 256;
            int br = lin >> 5, bc = (lin & 31) * 4;
            *(float4*)&Bs[br][bc] = pb[it];
        }
        __syncthreads();

        // prefetch next slab
        if (s + 1 < nk0) {
            int k0 = (s + 1) * BK;
#pragma unroll
            for (int it = 0; it < 2; it++) {
                int lin = a_lin0 + it * 256;
                int ar = lin >> 2, ac = (lin & 3) * 4;
                int gr = row0 + ar;
                pa[it] = make_float4(0.f, 0.f, 0.f, 0.f);
                if (gr < M) pa[it] = *(const float4*)&A[(size_t)gr * K + k0 + ac];
            }
#pragma unroll
            for (int it = 0; it < 2; it++) {
                int lin = tid + it * 256;
                int br = lin >> 5, bc = (lin & 31) * 4;
                int gc = col0 + bc;
                pb[it] = make_float4(0.f, 0.f, 0.f, 0.f);
                if (gc < N) pb[it] = *(const float4*)&B[(size_t)(k0 + br) * N + gc];
            }
        }

        // compute over current slab
#pragma unroll
        for (int k = 0; k < BK; k++) {
            float4 a0 = *(const float4*)&As[k][ty * 8];
            float4 a1 = *(const float4*)&As[k][ty * 8 + 4];
            // B pairs: read as packed 64-bit lanes directly
            ulonglong2 b01 = *(const ulonglong2*)&Bs[k][tx * 8];
            ulonglong2 b23 = *(const ulonglong2*)&Bs[k][tx * 8 + 4];
            unsigned long long b2[4] = {b01.x, b01.y, b23.x, b23.y};
            unsigned long long a2[8];
            a2[0] = pack2(a0.x, a0.x); a2[1] = pack2(a0.y, a0.y);
            a2[2] = pack2(a0.z, a0.z); a2[3] = pack2(a0.w, a0.w);
            a2[4] = pack2(a1.x, a1.x); a2[5] = pack2(a1.y, a1.y);
            a2[6] = pack2(a1.z, a1.z); a2[7] = pack2(a1.w, a1.w);
#pragma unroll
            for (int i = 0; i < 8; i++)
#pragma unroll
                for (int j = 0; j < 4; j++)
                    acc[i][j] = ffma2(a2[i], b2[j], acc[i][j]);
        }
        __syncthreads();
    }

    // epilogue
#pragma unroll
    for (int i = 0; i < 8; i++) {
        int r = row0 + ty * 8 + i;
        if (r >= M) continue;
#pragma unroll
        for (int j = 0; j < 4; j++) {
            int c = col0 + tx * 8 + j * 2;
            if (c < N) {   // pair-aligned; N even so both lanes valid
                float2 v = unpack2(acc[i][j]);
                *(float2*)&C[(size_t)r * N + c] = v;
            }
        }
    }
}

// ---------------- alpha_src / alpha_dst ----------------
__global__ void alpha_kernel(const float* __restrict__ xh,
                             const float* __restrict__ a_src,
                             const float* __restrict__ a_dst,
                             float* __restrict__ out_s, float* __restrict__ out_d)
{
    int n = blockIdx.x;
    int h = threadIdx.x >> 5;
    int lane = threadIdx.x & 31;
    const float* row = xh + (size_t)n * FEAT + h * DHEAD;
    const float* vs = a_src + h * DHEAD;
    const float* vd = a_dst + h * DHEAD;
    float s1 = 0.f, s2 = 0.f;
    for (int i = lane; i < DHEAD; i += 32) {
        float v = row[i];
        s1 = fmaf(v, vs[i], s1);
        s2 = fmaf(v, vd[i], s2);
    }
#pragma unroll
    for (int o = 16; o; o >>= 1) {
        s1 += __shfl_xor_sync(0xFFFFFFFFu, s1, o);
        s2 += __shfl_xor_sync(0xFFFFFFFFu, s2, o);
    }
    if (lane == 0) {
        out_s[n * NHEADS + h] = s1;
        out_d[n * NHEADS + h] = s2;
    }
}

// ---------------- edge pass A: segment max ----------------
__global__ void edge_max_kernel(const int* __restrict__ src, const int* __restrict__ dst,
                                int E, const float* __restrict__ as_,
                                const float* __restrict__ ad_, unsigned int* __restrict__ emax)
{
    int idx = blockIdx.x * blockDim.x + threadIdx.x;
    int total = (E + NNODES) * NHEADS;
    if (idx >= total) return;
    int e = idx >> 3;
    int h = idx & 7;
    int s, d;
    if (e < E) { s = src[e]; d = dst[e]; }
    else       { s = e - E; d = s; }
    float v = as_[s * NHEADS + h] + ad_[d * NHEADS + h];
    v = (v > 0.f) ? v : NEG_SLOPE * v;
    atomicMax(&emax[d * NHEADS + h], f2key(v));
}

// ---------------- edge pass B: exp + denom ----------------
__global__ void edge_exp_kernel(const int* __restrict__ src, const int* __restrict__ dst,
                                int E, const float* __restrict__ as_,
                                const float* __restrict__ ad_,
                                const unsigned int* __restrict__ emax,
                                float* __restrict__ exbuf, float* __restrict__ denom)
{
    int idx = blockIdx.x * blockDim.x + threadIdx.x;
    int total = (E + NNODES) * NHEADS;
    if (idx >= total) return;
    int e = idx >> 3;
    int h = idx & 7;
    int s, d;
    if (e < E) { s = src[e]; d = dst[e]; }
    else       { s = e - E; d = s; }
    float v = as_[s * NHEADS + h] + ad_[d * NHEADS + h];
    v = (v > 0.f) ? v : NEG_SLOPE * v;
    float m = key2f(emax[d * NHEADS + h]);
    float ex = expf(v - m);
    exbuf[idx] = ex;
    atomicAdd(&denom[d * NHEADS + h], ex);
}

// ---------------- edge pass C: weighted scatter ----------------
__global__ __launch_bounds__(256) void edge_scatter_kernel(
    const int* __restrict__ src, const int* __restrict__ dst, int E,
    const float* __restrict__ xh, const float* __restrict__ exbuf,
    const float* __restrict__ denom, float* __restrict__ att)
{
    int e = blockIdx.x;
    int s, d;
    if (e < E) { s = src[e]; d = dst[e]; }
    else       { s = e - E; d = s; }
    __shared__ float alpha[NHEADS];
    if (threadIdx.x < NHEADS)
        alpha[threadIdx.x] = exbuf[e * NHEADS + threadIdx.x] / denom[d * NHEADS + threadIdx.x];
    __syncthreads();
    const float* xrow = xh + (size_t)s * FEAT;
    float* orow = att + (size_t)d * FEAT;
    for (int c = threadIdx.x; c < FEAT; c += 256) {
        int h = c / DHEAD;
        atomicAdd(&orow[c], alpha[h] * xrow[c]);
    }
}

// ---------------- BN(eval) + bias + residual + relu ----------------
__global__ void bn_kernel(const float* __restrict__ att, const float* __restrict__ prev,
                          const float* __restrict__ b_att, const float* __restrict__ gamma,
                          const float* __restrict__ beta, const float* __restrict__ mean,
                          const float* __restrict__ var, float* __restrict__ out)
{
    int idx = blockIdx.x * blockDim.x + threadIdx.x;
    if (idx >= NNODES * FEAT) return;
    int c = idx % FEAT;
    float z = att[idx] + b_att[c];
    if (prev) z += prev[idx];
    z = (z - mean[c]) * rsqrtf(var[c] + BN_EPS) * gamma[c] + beta[c];
    out[idx] = (z > 0.f) ? z : 0.f;
}

// ---------------- pooling ----------------
__global__ void count_kernel(const int* __restrict__ batch, int N) {
    int n = blockIdx.x * blockDim.x + threadIdx.x;
    if (n < N) atomicAdd(&g_counts[batch[n]], 1.0f);
}
__global__ void pool_kernel(const int* __restrict__ batch, const float* __restrict__ h, int N) {
    int idx = blockIdx.x * blockDim.x + threadIdx.x;
    if (idx >= N * FEAT) return;
    int n = idx / FEAT;
    int c = idx - n * FEAT;
    atomicAdd(&g_pooled[batch[n] * FEAT + c], h[idx]);
}

// ---------------- final head ----------------
__global__ void head_kernel(const float* __restrict__ W_out, const float* __restrict__ b_out,
                            float* __restrict__ out)
{
    int g = blockIdx.x;
    int tid = threadIdx.x;  // 128
    float cnt = fmaxf(g_counts[g], 1.0f);
    float inv = 1.0f / cnt;
    float s0 = 0.f, s1 = 0.f;
    for (int c = tid; c < FEAT; c += 128) {
        float p = g_pooled[g * FEAT + c] * inv;
        s0 = fmaf(p, W_out[2 * c + 0], s0);
        s1 = fmaf(p, W_out[2 * c + 1], s1);
    }
#pragma unroll
    for (int o = 16; o; o >>= 1) {
        s0 += __shfl_xor_sync(0xFFFFFFFFu, s0, o);
        s1 += __shfl_xor_sync(0xFFFFFFFFu, s1, o);
    }
    __shared__ float r0[4], r1[4];
    if ((tid & 31) == 0) { r0[tid >> 5] = s0; r1[tid >> 5] = s1; }
    __syncthreads();
    if (tid == 0) {
        out[g * 2 + 0] = r0[0] + r0[1] + r0[2] + r0[3] + b_out[0];
        out[g * 2 + 1] = r1[0] + r1[1] + r1[2] + r1[3] + b_out[1];
    }
}

// ---------------- host launcher ----------------
extern "C" void kernel_launch(void* const* d_in, const int* in_sizes, int n_in,
                              void* d_out, int out_size)
{
    const float* x        = (const float*)d_in[0];
    const int*   edge_idx = (const int*)  d_in[1];
    const int*   batch    = (const int*)  d_in[2];
    const float* W        = (const float*)d_in[3];
    const float* a_src    = (const float*)d_in[4];
    const float* a_dst    = (const float*)d_in[5];
    const float* b_att    = (const float*)d_in[6];
    const float* gamma    = (const float*)d_in[7];
    const float* beta     = (const float*)d_in[8];
    const float* run_mean = (const float*)d_in[9];
    const float* run_var  = (const float*)d_in[10];
    const float* W_out    = (const float*)d_in[11];
    const float* b_out    = (const float*)d_in[12];
    float* out = (float*)d_out;

    int N = in_sizes[0] / FEAT;
    int E = in_sizes[1] / 2;
    const int* src = edge_idx;
    const int* dst = edge_idx + E;
    int E2 = E + N;

    float *p_xh, *p_att, *p_h0, *p_h1, *p_as, *p_ad, *p_denom, *p_ex, *p_pooled, *p_counts;
    unsigned int* p_emax;
    cudaGetSymbolAddress((void**)&p_xh, g_xh);
    cudaGetSymbolAddress((void**)&p_att, g_att);
    cudaGetSymbolAddress((void**)&p_h0, g_h0);
    cudaGetSymbolAddress((void**)&p_h1, g_h1);
    cudaGetSymbolAddress((void**)&p_as, g_as);
    cudaGetSymbolAddress((void**)&p_ad, g_ad);
    cudaGetSymbolAddress((void**)&p_emax, g_emax);
    cudaGetSymbolAddress((void**)&p_denom, g_denom);
    cudaGetSymbolAddress((void**)&p_ex, g_ex);
    cudaGetSymbolAddress((void**)&p_pooled, g_pooled);
    cudaGetSymbolAddress((void**)&p_counts, g_counts);

    dim3 gemm_grid((FEAT + BN - 1) / BN, (N + BM - 1) / BM);
    int nf = N * FEAT;
    int nh = N * NHEADS;
    int eh = E2 * NHEADS;

    const float* layer_in[3]   = {x, p_h0, p_h1};
    const float* layer_prev[3] = {nullptr, x, p_h0};
    float*       layer_out[3]  = {p_h0, p_h1, p_h0};

    for (int l = 0; l < 3; l++) {
        const float* Wl = W + (size_t)l * FEAT * FEAT;
        sgemm_f32x2_kernel<<<gemm_grid, 256>>>(layer_in[l], Wl, p_xh, N, FEAT, FEAT);
        alpha_kernel<<<N, 256>>>(p_xh, a_src + l * NHEADS * DHEAD, a_dst + l * NHEADS * DHEAD,
                                 p_as, p_ad);
        zero_u32<<<(nh + 255) / 256, 256>>>(p_emax, nh);
        zero_f32<<<(nh + 255) / 256, 256>>>(p_denom, nh);
        zero_f32<<<(nf + 255) / 256, 256>>>(p_att, nf);
        edge_max_kernel<<<(eh + 255) / 256, 256>>>(src, dst, E, p_as, p_ad, p_emax);
        edge_exp_kernel<<<(eh + 255) / 256, 256>>>(src, dst, E, p_as, p_ad, p_emax, p_ex, p_denom);
        edge_scatter_kernel<<<E2, 256>>>(src, dst, E, p_xh, p_ex, p_denom, p_att);
        bn_kernel<<<(nf + 255) / 256, 256>>>(p_att, layer_prev[l], b_att + l * FEAT,
                                             gamma + l * FEAT, beta + l * FEAT,
                                             run_mean + l * FEAT, run_var + l * FEAT,
                                             layer_out[l]);
    }

    zero_f32<<<(NGRAPHS * FEAT + 255) / 256, 256>>>(p_pooled, NGRAPHS * FEAT);
    zero_f32<<<1, NGRAPHS>>>(p_counts, NGRAPHS);
    count_kernel<<<(N + 255) / 256, 256>>>(batch, N);
    pool_kernel<<<(nf + 255) / 256, 256>>>(batch, layer_out[2], N);
    head_kernel<<<NGRAPHS, 128>>>(W_out, b_out, out);
}